// round 3
// baseline (speedup 1.0000x reference)
#include <cuda_runtime.h>
#include <cstdint>

// Nearest codeword on grid g_i = i - 7.5, i in [0,15]:
//   g(x) = clamp(ceil(x) - 0.5, -7.5, 7.5)  (ties -> lower codeword, matches argmax)
//   idx  = g + 7.5
__device__ __forceinline__ void quant1(float x, float& g, float& id) {
    float q = ceilf(x) - 0.5f;
    q = fminf(fmaxf(q, -7.5f), 7.5f);
    g = q;
    id = q + 7.5f;
}

__device__ __forceinline__ float4 quant4_vals(float4 v, float4& id) {
    float4 g;
    quant1(v.x, g.x, id.x);
    quant1(v.y, g.y, id.y);
    quant1(v.z, g.z, id.z);
    quant1(v.w, g.w, id.w);
    return g;
}

// 8 float4s per thread, block-strided (fully coalesced), loads front-batched
// for MLP. Default cache ops so the 96MB working set can stay L2-resident
// across graph replays (L2 = 126MB).
constexpr int ITEMS = 8;

__global__ void __launch_bounds__(256) quant_kernel_f32f32(
    const float4* __restrict__ x,
    float4* __restrict__ vals,
    float4* __restrict__ idxf,
    int n4) {
    int base = blockIdx.x * (blockDim.x * ITEMS) + threadIdx.x;
    int stride = blockDim.x;

    float4 v[ITEMS];
#pragma unroll
    for (int k = 0; k < ITEMS; k++) {
        v[k] = x[base + k * stride];          // n4 divisible by 256*ITEMS (2M / 2048)
    }
#pragma unroll
    for (int k = 0; k < ITEMS; k++) {
        int i = base + k * stride;
        float4 id;
        float4 g = quant4_vals(v[k], id);
        vals[i] = g;
        idxf[i] = id;
    }
}

// Fallback paths (other output layouts), kept for safety.
__global__ void quant_kernel_f32u8(const float4* __restrict__ x,
                                   float4* __restrict__ vals,
                                   uchar4* __restrict__ idxb,
                                   int n4) {
    int i = blockIdx.x * blockDim.x + threadIdx.x;
    if (i >= n4) return;
    float4 id;
    float4 g = quant4_vals(x[i], id);
    vals[i] = g;
    idxb[i] = make_uchar4((unsigned char)id.x, (unsigned char)id.y,
                          (unsigned char)id.z, (unsigned char)id.w);
}

__global__ void quant_kernel_valsonly(const float4* __restrict__ x,
                                      float4* __restrict__ vals,
                                      int n4) {
    int i = blockIdx.x * blockDim.x + threadIdx.x;
    if (i >= n4) return;
    float4 id;
    float4 g = quant4_vals(x[i], id);
    vals[i] = g;
}

extern "C" void kernel_launch(void* const* d_in, const int* in_sizes, int n_in,
                              void* d_out, int out_size) {
    const float* x = (const float*)d_in[0];
    int n = in_sizes[0];           // 8388608
    int n4 = n >> 2;               // 2M float4s
    const int threads = 256;

    if (out_size == 2 * n && (n4 % (threads * ITEMS)) == 0) {
        float* out = (float*)d_out;
        int blocks = n4 / (threads * ITEMS);   // 1024
        quant_kernel_f32f32<<<blocks, threads>>>(
            (const float4*)x, (float4*)out, (float4*)(out + n), n4);
    } else if (out_size == 5 * n) {
        uint8_t* out = (uint8_t*)d_out;
        int blocks = (n4 + threads - 1) / threads;
        quant_kernel_f32u8<<<blocks, threads>>>(
            (const float4*)x, (float4*)out, (uchar4*)(out + (size_t)4 * n), n4);
    } else {
        int blocks = (n4 + threads - 1) / threads;
        quant_kernel_valsonly<<<blocks, threads>>>(
            (const float4*)x, (float4*)d_out, n4);
    }
}

// round 4
// speedup vs baseline: 1.3134x; 1.3134x over previous
#include <cuda_runtime.h>
#include <cstdint>

// Nearest codeword on grid g_i = i - 7.5, i in [0,15]:
//   g(x) = clamp(ceil(x) - 0.5, -7.5, 7.5)  (ties -> lower codeword, matches argmax)
//   idx  = g + 7.5
__device__ __forceinline__ void quant1(float x, float& g, float& id) {
    float q = ceilf(x) - 0.5f;
    q = fminf(fmaxf(q, -7.5f), 7.5f);
    g = q;
    id = q + 7.5f;
}

__device__ __forceinline__ float4 quant4_vals(float4 v, float4& id) {
    float4 g;
    quant1(v.x, g.x, id.x);
    quant1(v.y, g.y, id.y);
    quant1(v.z, g.z, id.z);
    quant1(v.w, g.w, id.w);
    return g;
}

// Cache policy: input loads DEFAULT (L2-retain across graph replays, 32MB fits
// easily in 126MB L2); output stores EVICT-FIRST (__stcs) so the 64MB/replay
// output stream does not churn L2 ways and evict the input.
constexpr int ITEMS = 4;

__global__ void __launch_bounds__(256) quant_kernel_f32f32(
    const float4* __restrict__ x,
    float4* __restrict__ vals,
    float4* __restrict__ idxf,
    int n4) {
    int base = blockIdx.x * (blockDim.x * ITEMS) + threadIdx.x;
    int stride = blockDim.x;

    float4 v[ITEMS];
#pragma unroll
    for (int k = 0; k < ITEMS; k++) {
        v[k] = x[base + k * stride];     // default policy: stays in L2
    }
#pragma unroll
    for (int k = 0; k < ITEMS; k++) {
        int i = base + k * stride;
        float4 id;
        float4 g = quant4_vals(v[k], id);
        __stcs(&vals[i], g);             // evict-first: stream through L2
        __stcs(&idxf[i], id);
    }
}

// Fallback paths (other output layouts), kept for safety.
__global__ void quant_kernel_f32u8(const float4* __restrict__ x,
                                   float4* __restrict__ vals,
                                   uchar4* __restrict__ idxb,
                                   int n4) {
    int i = blockIdx.x * blockDim.x + threadIdx.x;
    if (i >= n4) return;
    float4 id;
    float4 g = quant4_vals(x[i], id);
    __stcs(&vals[i], g);
    idxb[i] = make_uchar4((unsigned char)id.x, (unsigned char)id.y,
                          (unsigned char)id.z, (unsigned char)id.w);
}

__global__ void quant_kernel_valsonly(const float4* __restrict__ x,
                                      float4* __restrict__ vals,
                                      int n4) {
    int i = blockIdx.x * blockDim.x + threadIdx.x;
    if (i >= n4) return;
    float4 id;
    float4 g = quant4_vals(x[i], id);
    __stcs(&vals[i], g);
}

extern "C" void kernel_launch(void* const* d_in, const int* in_sizes, int n_in,
                              void* d_out, int out_size) {
    const float* x = (const float*)d_in[0];
    int n = in_sizes[0];           // 8388608
    int n4 = n >> 2;               // 2M float4s
    const int threads = 256;

    if (out_size == 2 * n && (n4 % (threads * ITEMS)) == 0) {
        float* out = (float*)d_out;
        int blocks = n4 / (threads * ITEMS);   // 2048
        quant_kernel_f32f32<<<blocks, threads>>>(
            (const float4*)x, (float4*)out, (float4*)(out + n), n4);
    } else if (out_size == 5 * n) {
        uint8_t* out = (uint8_t*)d_out;
        int blocks = (n4 + threads - 1) / threads;
        quant_kernel_f32u8<<<blocks, threads>>>(
            (const float4*)x, (float4*)out, (uchar4*)(out + (size_t)4 * n), n4);
    } else {
        int blocks = (n4 + threads - 1) / threads;
        quant_kernel_valsonly<<<blocks, threads>>>(
            (const float4*)x, (float4*)d_out, n4);
    }
}